// round 12
// baseline (speedup 1.0000x reference)
#include <cuda_runtime.h>
#include <math.h>

#define BATCH  4096
#define NMODES 512
#define NLU    128
#define NB     8
#define JB     16
#define LDA    130   /* even row stride: 8B-aligned float2 smem ops */

typedef unsigned long long ull;

// ---------------- scratch (static device globals; no allocation) ----------------
__device__ int   g_idx[BATCH * 256];
__device__ float g_logj[BATCH];
__device__ float g_sign[BATCH * 2];
__device__ float g_labs[BATCH * 2];

// ---------------- kernel 1: occupied-index extraction ---------------------------
__global__ void idx_kernel(const int* __restrict__ n) {
    int b = blockIdx.x;
    int t = threadIdx.x;
    __shared__ int wcu[8], wcd[8];
    int vu = n[b * NMODES + t];
    int vd = n[b * NMODES + 256 + t];
    unsigned mu = __ballot_sync(0xffffffffu, vu != 0);
    unsigned md = __ballot_sync(0xffffffffu, vd != 0);
    int lane = t & 31, w = t >> 5;
    if (lane == 0) { wcu[w] = __popc(mu); wcd[w] = __popc(md); }
    __syncthreads();
    int bu = 0, bd = 0;
    for (int i = 0; i < w; i++) { bu += wcu[i]; bd += wcd[i]; }
    unsigned lt = (1u << lane) - 1u;
    if (vu) g_idx[b * 256 + bu + __popc(mu & lt)] = t;
    if (vd) g_idx[b * 256 + 128 + bd + __popc(md & lt)] = t;
}

// ---------------- kernel 2: Jastrow ---------------------------------------------
__global__ __launch_bounds__(256) void jastrow_kernel(const int* __restrict__ n,
                                                      const float* __restrict__ v) {
    int b0 = blockIdx.x * JB;
    __shared__ float sn[JB][NMODES];
    __shared__ float spart[JB][8];
    int tid = threadIdx.x;
    for (int x = tid; x < JB * NMODES; x += 256)
        sn[x >> 9][x & 511] = (float)n[b0 * NMODES + x];
    __syncthreads();

    int j0 = tid * 2;
    float acc0[JB], acc1[JB];
#pragma unroll
    for (int bb = 0; bb < JB; bb++) { acc0[bb] = 0.f; acc1[bb] = 0.f; }

    for (int i = 0; i < NMODES; i++) {
        float2 vv = *reinterpret_cast<const float2*>(v + (size_t)i * NMODES + j0);
#pragma unroll
        for (int bb = 0; bb < JB; bb++) {
            float f = sn[bb][i];
            acc0[bb] += f * vv.x;
            acc1[bb] += f * vv.y;
        }
    }

    int lane = tid & 31, wrp = tid >> 5;
#pragma unroll
    for (int bb = 0; bb < JB; bb++) {
        float s = acc0[bb] * sn[bb][j0] + acc1[bb] * sn[bb][j0 + 1];
#pragma unroll
        for (int off = 16; off > 0; off >>= 1)
            s += __shfl_down_sync(0xffffffffu, s, off);
        if (lane == 0) spart[bb][wrp] = s;
    }
    __syncthreads();
    if (tid < JB) {
        float s = 0.f;
#pragma unroll
        for (int w = 0; w < 8; w++) s += spart[tid][w];
        g_logj[b0 + tid] = -0.5f * s;
    }
}

// ---------------- dummy kernel (ncu slot alignment: keeps lu at -s 5) -----------
__global__ void pad_kernel() {}

// ---------------- kernel 3: blocked LU (register panel, f32x2 GEMM) -------------
extern __shared__ float As[];
#define A(i, j) As[(i) * LDA + (j)]

__global__ __launch_bounds__(256, 3) void lu_kernel(const float* __restrict__ phi_up,
                                                    const float* __restrict__ phi_dn) {
    int cta  = blockIdx.x;
    int b    = cta >> 1;
    int spin = cta & 1;
    const float* __restrict__ phi = spin ? phi_dn : phi_up;
    const int*   __restrict__ idx = g_idx + b * 256 + spin * 128;

    __shared__ int s_pivlist[NB];

    int tid  = threadIdx.x;
    int lane = tid & 31;

    // gather phase A: panel-0 columns (0..7) only — enough to start factoring
    for (int e = tid; e < NLU * NB; e += 256) {
        int r = e >> 3, c = e & 7;
        A(r, c) = phi[idx[r] * NLU + c];
    }

    float t_logabs = 0.f;
    float t_sign   = 1.f;

    int tx = tid & 15, ty = tid >> 4;

    for (int k0 = 0; k0 < NLU; k0 += NB) {
        __syncthreads();   // trailing matrix (incl. this panel) up to date

        // ===== single-warp REGISTER panel factorization (warp 0) =================
        if (tid < 32) {
            float p[4][NB];
            int   pos[4];
            bool  done[4];
#pragma unroll
            for (int s = 0; s < 4; s++) {
                int r = lane + 32 * s;
                done[s] = (r < k0);
#pragma unroll
                for (int c = 0; c < NB; c++)
                    p[s][c] = done[s] ? 0.f : A(r, k0 + c);
                pos[s] = r;
            }
            float ur[NB];
            float mp = 1.f;      // mantissa product
            int   es = 0;        // exponent sum
#pragma unroll
            for (int kk = 0; kk < NB; kk++) {
                int kabs = k0 + kk;
                unsigned best = 0u;
#pragma unroll
                for (int s = 0; s < 4; s++) {
                    if (!done[s]) {
                        unsigned ab  = __float_as_uint(p[s][kk]) & 0x7FFFFFFFu;
                        unsigned key = (ab & 0xFFFFFF80u) | (unsigned)(lane + 32 * s);
                        if (key > best) best = key;
                    }
                }
                best = __reduce_max_sync(0xffffffffu, best);
                int prr = (int)(best & 0x7Fu);
                int psl = prr >> 5, pln = prr & 31;
#pragma unroll
                for (int c = 0; c < NB; c++) {
                    if (c >= kk) {       // live columns only (halved shuffles)
                        float tv = (psl == 0) ? p[0][c] : (psl == 1) ? p[1][c]
                                  : (psl == 2) ? p[2][c] : p[3][c];
                        ur[c] = __shfl_sync(0xffffffffu, tv, pln);
                    }
                }
                int tq = (psl == 0) ? pos[0] : (psl == 1) ? pos[1]
                        : (psl == 2) ? pos[2] : pos[3];
                int qp = __shfl_sync(0xffffffffu, tq, pln);

                float piv = ur[kk];
                unsigned pb = __float_as_uint(piv) & 0x7FFFFFFFu;
                es += (int)(pb >> 23) - 127;
                mp *= __uint_as_float((pb & 0x007FFFFFu) | 0x3F800000u);
                if (piv < 0.f)  t_sign = -t_sign;
                if (qp != kabs) t_sign = -t_sign;
                if (lane == 0)  s_pivlist[kk] = qp;

#pragma unroll
                for (int s = 0; s < 4; s++) {
                    int r = lane + 32 * s;
                    if (r == prr) { pos[s] = kabs; done[s] = true; }
                    else if (!done[s] && pos[s] == kabs) pos[s] = qp;
                }
                float inv = __fdividef(1.0f, piv);
#pragma unroll
                for (int s = 0; s < 4; s++) {
                    if (!done[s]) {
                        float mll = p[s][kk] * inv;
                        p[s][kk] = mll;
#pragma unroll
                        for (int c = kk + 1; c < NB; c++)
                            p[s][c] -= mll * ur[c];
                    }
                }
            }
            t_logabs += __logf(mp) + (float)es * 0.6931471805599453f;
            __syncwarp();
            // writeback; below-diagonal (L) entries stored NEGATED (f32x2 GEMM)
#pragma unroll
            for (int s = 0; s < 4; s++) {
                if (lane + 32 * s >= k0) {
                    int d = pos[s] - k0;
#pragma unroll
                    for (int c = 0; c < NB; c++) {
                        float val = p[s][c];
                        A(pos[s], k0 + c) = (c < d) ? -val : val;
                    }
                }
            }
        } else if (k0 == 0) {
            // gather phase B: cols 8..127 while warp 0 factors panel 0
            int w = tid >> 5;                    // 1..7
            for (int r = w - 1; r < NLU; r += 7) {
                const float* src = phi + idx[r] * NLU;
                for (int c = NB + lane; c < NLU; c += 32)
                    A(r, c) = src[c];
            }
        }
        __syncthreads();   // panel + pivot list visible to all warps

        int base = k0 + NB;
        int m2 = NLU - base;

        if (m2 > 0) {
            // ===== fused: apply row swaps + TRSM (L stored negated) ==============
            for (int j = base + tid; j < NLU; j += 256) {
#pragma unroll
                for (int k = 0; k < NB; k++) {
                    int qp = s_pivlist[k];
                    int kr = k0 + k;
                    if (qp != kr) {
                        float a0 = A(kr, j), b0 = A(qp, j);
                        A(kr, j) = b0; A(qp, j) = a0;
                    }
                }
                float u[NB];
#pragma unroll
                for (int rr = 0; rr < NB; rr++) {
                    float x = A(k0 + rr, j);
#pragma unroll
                    for (int t = 0; t < NB; t++)
                        if (t < rr) x += A(k0 + rr, k0 + t) * u[t];   // Lneg
                    u[rr] = x;
                    A(k0 + rr, j) = x;
                }
            }
            __syncthreads();

            // ===== trailing GEMM: A22 += Lneg21 * U12, f32x2, hoisted la =========
            for (int sa = 0; sa < m2; sa += 64) {
                int rw[4];  bool rv[4];
#pragma unroll
                for (int a = 0; a < 4; a++) {
                    int ro = sa + ty + 16 * a;
                    rv[a] = (ro < m2);
                    rw[a] = (base + (rv[a] ? ro : (m2 - 1))) * LDA;
                }
                // hoist la for this row stripe: reused across all sb tiles
                float laf[4][NB];
#pragma unroll
                for (int a = 0; a < 4; a++)
#pragma unroll
                for (int t = 0; t < NB; t++)
                    laf[a][t] = As[rw[a] + k0 + t];

                for (int sb = 0; sb < m2; sb += 64) {
                    int jw[2]; bool cv[2];
#pragma unroll
                    for (int c = 0; c < 2; c++) {
                        int co = sb + 2 * tx + 32 * c;
                        cv[c] = (co < m2);
                        jw[c] = base + (cv[c] ? co : 0);
                    }
                    ull acc[4][2];
#pragma unroll
                    for (int a = 0; a < 4; a++)
#pragma unroll
                    for (int c = 0; c < 2; c++)
                        acc[a][c] = *reinterpret_cast<const ull*>(&As[rw[a] + jw[c]]);
#pragma unroll
                    for (int t = 0; t < NB; t++) {
                        ull lb0 = *reinterpret_cast<const ull*>(&As[(k0 + t) * LDA + jw[0]]);
                        ull lb1 = *reinterpret_cast<const ull*>(&As[(k0 + t) * LDA + jw[1]]);
#pragma unroll
                        for (int a = 0; a < 4; a++) {
                            ull lad;
                            asm("mov.b64 %0, {%1, %1};" : "=l"(lad) : "f"(laf[a][t]));
                            asm("fma.rn.f32x2 %0, %1, %2, %0;" : "+l"(acc[a][0])
                                : "l"(lad), "l"(lb0));
                            asm("fma.rn.f32x2 %0, %1, %2, %0;" : "+l"(acc[a][1])
                                : "l"(lad), "l"(lb1));
                        }
                    }
#pragma unroll
                    for (int a = 0; a < 4; a++)
#pragma unroll
                    for (int c = 0; c < 2; c++)
                        if (rv[a] && cv[c])
                            *reinterpret_cast<ull*>(&As[rw[a] + jw[c]]) = acc[a][c];
                }
            }
        }
    }

    if (tid == 0) {
        g_sign[cta] = t_sign;
        g_labs[cta] = t_logabs;
    }
}

// ---------------- kernel 4: combine ---------------------------------------------
__global__ void combine_kernel(float* __restrict__ out) {
    int b = blockIdx.x * 256 + threadIdx.x;
    if (b < BATCH) {
        out[b]         = g_sign[2 * b] * g_sign[2 * b + 1];
        out[BATCH + b] = g_logj[b] + g_labs[2 * b] + g_labs[2 * b + 1];
    }
}

// ---------------- launch ---------------------------------------------------------
extern "C" void kernel_launch(void* const* d_in, const int* in_sizes, int n_in,
                              void* d_out, int out_size) {
    const int*   n      = (const int*)d_in[0];
    const float* phi_up = (const float*)d_in[1];
    const float* phi_dn = (const float*)d_in[2];
    const float* v      = (const float*)d_in[3];
    float* out = (float*)d_out;

    const int LU_SMEM = NLU * LDA * (int)sizeof(float);   // 66560 B
    cudaFuncSetAttribute(lu_kernel, cudaFuncAttributeMaxDynamicSharedMemorySize, LU_SMEM);

    idx_kernel<<<BATCH, 256>>>(n);
    jastrow_kernel<<<BATCH / JB, 256>>>(n, v);
    pad_kernel<<<1, 32>>>();                       // keeps lu_kernel at ncu -s 5
    lu_kernel<<<BATCH * 2, 256, LU_SMEM>>>(phi_up, phi_dn);
    combine_kernel<<<(BATCH + 255) / 256, 256>>>(out);
}

// round 13
// speedup vs baseline: 1.0616x; 1.0616x over previous
#include <cuda_runtime.h>
#include <math.h>

#define BATCH  4096
#define NMODES 512
#define NLU    128
#define NB     8
#define JB     16
#define LDA    130   /* even row stride: enables 8B-aligned float2 smem ops */

typedef unsigned long long ull;

// ---------------- scratch (static device globals; no allocation) ----------------
__device__ int   g_idx[BATCH * 256];
__device__ float g_logj[BATCH];
__device__ float g_sign[BATCH * 2];
__device__ float g_labs[BATCH * 2];

// ---------------- kernel 1: occupied-index extraction ---------------------------
__global__ void idx_kernel(const int* __restrict__ n) {
    int b = blockIdx.x;
    int t = threadIdx.x;
    __shared__ int wcu[8], wcd[8];
    int vu = n[b * NMODES + t];
    int vd = n[b * NMODES + 256 + t];
    unsigned mu = __ballot_sync(0xffffffffu, vu != 0);
    unsigned md = __ballot_sync(0xffffffffu, vd != 0);
    int lane = t & 31, w = t >> 5;
    if (lane == 0) { wcu[w] = __popc(mu); wcd[w] = __popc(md); }
    __syncthreads();
    int bu = 0, bd = 0;
    for (int i = 0; i < w; i++) { bu += wcu[i]; bd += wcd[i]; }
    unsigned lt = (1u << lane) - 1u;
    if (vu) g_idx[b * 256 + bu + __popc(mu & lt)] = t;
    if (vd) g_idx[b * 256 + 128 + bd + __popc(md & lt)] = t;
}

// ---------------- kernel 2: Jastrow ---------------------------------------------
__global__ __launch_bounds__(256) void jastrow_kernel(const int* __restrict__ n,
                                                      const float* __restrict__ v) {
    int b0 = blockIdx.x * JB;
    __shared__ float sn[JB][NMODES];
    __shared__ float spart[JB][8];
    int tid = threadIdx.x;
    for (int x = tid; x < JB * NMODES; x += 256)
        sn[x >> 9][x & 511] = (float)n[b0 * NMODES + x];
    __syncthreads();

    int j0 = tid * 2;
    float acc0[JB], acc1[JB];
#pragma unroll
    for (int bb = 0; bb < JB; bb++) { acc0[bb] = 0.f; acc1[bb] = 0.f; }

    for (int i = 0; i < NMODES; i++) {
        float2 vv = *reinterpret_cast<const float2*>(v + (size_t)i * NMODES + j0);
#pragma unroll
        for (int bb = 0; bb < JB; bb++) {
            float f = sn[bb][i];
            acc0[bb] += f * vv.x;
            acc1[bb] += f * vv.y;
        }
    }

    int lane = tid & 31, wrp = tid >> 5;
#pragma unroll
    for (int bb = 0; bb < JB; bb++) {
        float s = acc0[bb] * sn[bb][j0] + acc1[bb] * sn[bb][j0 + 1];
#pragma unroll
        for (int off = 16; off > 0; off >>= 1)
            s += __shfl_down_sync(0xffffffffu, s, off);
        if (lane == 0) spart[bb][wrp] = s;
    }
    __syncthreads();
    if (tid < JB) {
        float s = 0.f;
#pragma unroll
        for (int w = 0; w < 8; w++) s += spart[tid][w];
        g_logj[b0 + tid] = -0.5f * s;
    }
}

// ---------------- kernel 3: blocked LU (register panel, f32x2 GEMM) -------------
extern __shared__ float As[];
#define A(i, j) As[(i) * LDA + (j)]

__global__ __launch_bounds__(256, 3) void lu_kernel(const float* __restrict__ phi_up,
                                                    const float* __restrict__ phi_dn) {
    int cta  = blockIdx.x;
    int b    = cta >> 1;
    int spin = cta & 1;
    const float* __restrict__ phi = spin ? phi_dn : phi_up;
    const int*   __restrict__ idx = g_idx + b * 256 + spin * 128;

    __shared__ int s_pivlist[NB];

    int tid  = threadIdx.x;
    int lane = tid & 31;

    // gather M = phi[idx] into smem (coalesced)
    {
        int c = tid & 127, rh = tid >> 7;
        for (int it = 0; it < 64; it++) {
            int r = (it << 1) + rh;
            A(r, c) = phi[idx[r] * NLU + c];
        }
    }

    float t_logabs = 0.f;
    float t_sign   = 1.f;

    int tx = tid & 15, ty = tid >> 4;

    for (int k0 = 0; k0 < NLU; k0 += NB) {
        __syncthreads();   // trailing matrix (incl. this panel) up to date

        // ===== single-warp REGISTER panel factorization (warp 0) =================
        if (tid < 32) {
            float p[4][NB];
            int   pos[4];
            bool  done[4];
#pragma unroll
            for (int s = 0; s < 4; s++) {
                int r = lane + 32 * s;
                done[s] = (r < k0);
#pragma unroll
                for (int c = 0; c < NB; c++)
                    p[s][c] = done[s] ? 0.f : A(r, k0 + c);
                pos[s] = r;
            }
            float ur[NB];
            float mp = 1.f;      // mantissa product
            int   es = 0;        // exponent sum
#pragma unroll
            for (int kk = 0; kk < NB; kk++) {
                int kabs = k0 + kk;
                unsigned best = 0u;
#pragma unroll
                for (int s = 0; s < 4; s++) {
                    if (!done[s]) {
                        unsigned ab  = __float_as_uint(p[s][kk]) & 0x7FFFFFFFu;
                        unsigned key = (ab & 0xFFFFFF80u) | (unsigned)(lane + 32 * s);
                        if (key > best) best = key;
                    }
                }
                best = __reduce_max_sync(0xffffffffu, best);
                int prr = (int)(best & 0x7Fu);
                int psl = prr >> 5, pln = prr & 31;
#pragma unroll
                for (int c = 0; c < NB; c++) {
                    float tv = (psl == 0) ? p[0][c] : (psl == 1) ? p[1][c]
                              : (psl == 2) ? p[2][c] : p[3][c];
                    ur[c] = __shfl_sync(0xffffffffu, tv, pln);
                }
                int tq = (psl == 0) ? pos[0] : (psl == 1) ? pos[1]
                        : (psl == 2) ? pos[2] : pos[3];
                int qp = __shfl_sync(0xffffffffu, tq, pln);

                float piv = ur[kk];
                unsigned pb = __float_as_uint(piv) & 0x7FFFFFFFu;
                es += (int)(pb >> 23) - 127;
                mp *= __uint_as_float((pb & 0x007FFFFFu) | 0x3F800000u);
                if (piv < 0.f)  t_sign = -t_sign;
                if (qp != kabs) t_sign = -t_sign;
                if (lane == 0)  s_pivlist[kk] = qp;

#pragma unroll
                for (int s = 0; s < 4; s++) {
                    int r = lane + 32 * s;
                    if (r == prr) { pos[s] = kabs; done[s] = true; }
                    else if (!done[s] && pos[s] == kabs) pos[s] = qp;
                }
                float inv = __fdividef(1.0f, piv);
#pragma unroll
                for (int s = 0; s < 4; s++) {
                    if (!done[s]) {
                        float mll = p[s][kk] * inv;
                        p[s][kk] = mll;
#pragma unroll
                        for (int c = kk + 1; c < NB; c++)
                            p[s][c] -= mll * ur[c];
                    }
                }
            }
            t_logabs += __logf(mp) + (float)es * 0.6931471805599453f;
            __syncwarp();
            // writeback; below-diagonal (L) entries stored NEGATED so the
            // trailing update is a pure positive fma (enables f32x2 packing)
#pragma unroll
            for (int s = 0; s < 4; s++) {
                if (lane + 32 * s >= k0) {
                    int d = pos[s] - k0;     // final row offset within/below panel
#pragma unroll
                    for (int c = 0; c < NB; c++) {
                        float val = p[s][c];
                        A(pos[s], k0 + c) = (c < d) ? -val : val;
                    }
                }
            }
        }
        __syncthreads();   // panel + pivot list visible to all warps

        int base = k0 + NB;
        int m2 = NLU - base;

        if (m2 > 0) {
            // ===== fused: apply row swaps + TRSM (L stored negated) ==============
            for (int j = base + tid; j < NLU; j += 256) {
#pragma unroll
                for (int k = 0; k < NB; k++) {
                    int qp = s_pivlist[k];
                    int kr = k0 + k;
                    if (qp != kr) {
                        float a0 = A(kr, j), b0 = A(qp, j);
                        A(kr, j) = b0; A(qp, j) = a0;
                    }
                }
                float u[NB];
#pragma unroll
                for (int rr = 0; rr < NB; rr++) {
                    float x = A(k0 + rr, j);
#pragma unroll
                    for (int t = 0; t < NB; t++)
                        if (t < rr) x += A(k0 + rr, k0 + t) * u[t];   // Lneg
                    u[rr] = x;
                    A(k0 + rr, j) = x;
                }
            }
            __syncthreads();

            // ===== trailing GEMM: A22 += Lneg21 * U12, packed f32x2 ==============
            for (int sa = 0; sa < m2; sa += 64)
            for (int sb = 0; sb < m2; sb += 64) {
                int rw[4];  bool rv[4];
#pragma unroll
                for (int a = 0; a < 4; a++) {
                    int ro = sa + ty + 16 * a;
                    rv[a] = (ro < m2);
                    rw[a] = (base + (rv[a] ? ro : (m2 - 1))) * LDA;
                }
                int jw[2]; bool cv[2];
#pragma unroll
                for (int c = 0; c < 2; c++) {
                    int co = sb + 2 * tx + 32 * c;
                    cv[c] = (co < m2);            // pair-valid (m2 even)
                    jw[c] = base + (cv[c] ? co : 0);
                }
                ull acc[4][2];
#pragma unroll
                for (int a = 0; a < 4; a++)
#pragma unroll
                for (int c = 0; c < 2; c++)
                    acc[a][c] = *reinterpret_cast<const ull*>(&As[rw[a] + jw[c]]);
#pragma unroll
                for (int t = 0; t < NB; t++) {
                    ull lb0 = *reinterpret_cast<const ull*>(&As[(k0 + t) * LDA + jw[0]]);
                    ull lb1 = *reinterpret_cast<const ull*>(&As[(k0 + t) * LDA + jw[1]]);
#pragma unroll
                    for (int a = 0; a < 4; a++) {
                        float la = As[rw[a] + k0 + t];
                        ull lad;
                        asm("mov.b64 %0, {%1, %1};" : "=l"(lad) : "f"(la));
                        asm("fma.rn.f32x2 %0, %1, %2, %0;" : "+l"(acc[a][0])
                            : "l"(lad), "l"(lb0));
                        asm("fma.rn.f32x2 %0, %1, %2, %0;" : "+l"(acc[a][1])
                            : "l"(lad), "l"(lb1));
                    }
                }
#pragma unroll
                for (int a = 0; a < 4; a++)
#pragma unroll
                for (int c = 0; c < 2; c++)
                    if (rv[a] && cv[c])
                        *reinterpret_cast<ull*>(&As[rw[a] + jw[c]]) = acc[a][c];
            }
        }
    }

    if (tid == 0) {
        g_sign[cta] = t_sign;
        g_labs[cta] = t_logabs;
    }
}

// ---------------- kernel 4: combine ---------------------------------------------
__global__ void combine_kernel(float* __restrict__ out) {
    int b = blockIdx.x * 256 + threadIdx.x;
    if (b < BATCH) {
        out[b]         = g_sign[2 * b] * g_sign[2 * b + 1];
        out[BATCH + b] = g_logj[b] + g_labs[2 * b] + g_labs[2 * b + 1];
    }
}

// ---------------- launch: jastrow forked onto a side stream ----------------------
// Stream/events are created once (host-side driver objects, no device memory);
// every call records the identical 4-kernel fork-join node set, so the captured
// graph is deterministic and allocation-free.
extern "C" void kernel_launch(void* const* d_in, const int* in_sizes, int n_in,
                              void* d_out, int out_size) {
    const int*   n      = (const int*)d_in[0];
    const float* phi_up = (const float*)d_in[1];
    const float* phi_dn = (const float*)d_in[2];
    const float* v      = (const float*)d_in[3];
    float* out = (float*)d_out;

    static cudaStream_t s2 = 0;
    static cudaEvent_t  ev_fork = 0, ev_join = 0;
    static int s_init = 0;
    if (!s_init) {
        cudaStreamCreateWithFlags(&s2, cudaStreamNonBlocking);
        cudaEventCreateWithFlags(&ev_fork, cudaEventDisableTiming);
        cudaEventCreateWithFlags(&ev_join, cudaEventDisableTiming);
        const int LU_SMEM_I = NLU * LDA * (int)sizeof(float);
        cudaFuncSetAttribute(lu_kernel, cudaFuncAttributeMaxDynamicSharedMemorySize,
                             LU_SMEM_I);
        s_init = 1;
    }
    const int LU_SMEM = NLU * LDA * (int)sizeof(float);   // 66560 B

    // fork: jastrow (independent of idx/lu) runs on s2 concurrently with lu
    cudaEventRecord(ev_fork, 0);
    cudaStreamWaitEvent(s2, ev_fork, 0);
    jastrow_kernel<<<BATCH / JB, 256, 0, s2>>>(n, v);
    cudaEventRecord(ev_join, s2);

    idx_kernel<<<BATCH, 256>>>(n);
    lu_kernel<<<BATCH * 2, 256, LU_SMEM>>>(phi_up, phi_dn);

    // join: combine needs g_logj (s2) and g_sign/g_labs (main)
    cudaStreamWaitEvent(0, ev_join, 0);
    combine_kernel<<<(BATCH + 255) / 256, 256>>>(out);
}